// round 2
// baseline (speedup 1.0000x reference)
#include <cuda_runtime.h>
#include <math.h>

// Problem constants
#define P_TOT   16200   // H*W = 90*180
#define MD      130     // MODEL_DIM
#define L       128     // learned channels
#define NH      8
#define HD      16
#define S       16
#define K       25
#define NNB     25
#define MH      32
#define FH      256

// Scratch (allocation-free: __device__ globals)
__device__ __align__(16) float g_xmix[P_TOT * L];   // 8.3 MB
__device__ __align__(16) float g_hf  [P_TOT * FH];  // 16.6 MB

__device__ __forceinline__ float gelu_f(float v) {
    // exact GELU: x * 0.5 * (1 + erf(x/sqrt(2)))
    return 0.5f * v * (1.0f + erff(v * 0.70710678118654752f));
}

// ============================================================================
// Kernel A: disco conv (refactored) + per-head MLP + residual -> g_xmix
//   One block (128 threads) processes PPB_A pixels sequentially.
//   Per pixel:  W2[n][s] = sum_k disco_w[s][k] * basis[k][p][n]
//               y[c][s]  = sum_n G[c][n] * W2[n][s] + disco_b[s]
//               heads:   h1 = gelu(y_row @ w1[h] + b1), hout = h1g @ w2[h] + b2
//               x_mix[c] = hout + x_res[c]
// ============================================================================
#define PPB_A 25
__global__ void __launch_bounds__(128) disco_heads_kernel(
    const float* __restrict__ x,
    const int*   __restrict__ nbr,
    const float* __restrict__ basis,
    const float* __restrict__ dw,
    const float* __restrict__ db,
    const float* __restrict__ hw1,
    const float* __restrict__ hb1,
    const float* __restrict__ hw2,
    const float* __restrict__ hb2,
    float* __restrict__ out)
{
    __shared__ __align__(16) float s_dw[S * K];          // 400
    __shared__ __align__(16) float s_db[S];              // 16
    __shared__ __align__(16) float s_w1[NH * S * MH];    // 4096
    __shared__ __align__(16) float s_b1[NH * MH];        // 256
    __shared__ __align__(16) float s_w2[NH * MH];        // 256
    __shared__ __align__(16) float s_b2[NH];             // 8
    __shared__ __align__(16) float s_basis[K * NNB + 3]; // 625 (+pad)
    __shared__ __align__(16) float s_wp[NNB * S];        // 400, [n][s]
    __shared__ __align__(16) float s_G[NNB * L];         // 3200, [n][c]
    __shared__ __align__(16) float s_y[L * 17];          // 2176, [c][s] padded row 17
    __shared__ int   s_nbr[NNB];

    const int t = threadIdx.x;

    // Load block-invariant weights once
    for (int i = t; i < S * K; i += 128) s_dw[i] = dw[i];
    if (t < S) s_db[t] = db[t];
    for (int i = t; i < NH * S * MH; i += 128) s_w1[i] = hw1[i];
    for (int i = t; i < NH * MH; i += 128) { s_b1[i] = hb1[i]; s_w2[i] = hw2[i]; }
    if (t < NH) s_b2[t] = hb2[t];

    const int p0 = blockIdx.x * PPB_A;

    for (int ip = 0; ip < PPB_A; ip++) {
        const int p = p0 + ip;

        __syncthreads();  // protect smem reused from previous pixel

        if (t < NNB) s_nbr[t] = nbr[p * NNB + t];
        for (int i = t; i < K * NNB; i += 128) {
            const int k = i / NNB, n = i - k * NNB;
            s_basis[i] = basis[(k * P_TOT + p) * NNB + n];
        }
        __syncthreads();

        // residual value (thread t = channel c) + pass-through sin/cos
        const float xres = x[p * MD + t];
        if (t < 2) out[p * MD + L + t] = x[p * MD + L + t];

        // gather: G[n][c] = x[nbr[n]][c]  (coalesced 512B per neighbor row)
        #pragma unroll
        for (int n = 0; n < NNB; n++) {
            const int q = s_nbr[n];
            s_G[n * L + t] = x[q * MD + t];
        }

        // W2[n][s] = sum_k dw[s][k] * basis[k][n]   (400 outputs)
        for (int i = t; i < NNB * S; i += 128) {
            const int n = i >> 4, s = i & 15;
            float a = 0.f;
            #pragma unroll
            for (int k = 0; k < K; k++)
                a = fmaf(s_dw[s * K + k], s_basis[k * NNB + n], a);
            s_wp[i] = a;
        }
        __syncthreads();

        // y[c][s] = sum_n G[c][n] * W2[n][s] + db[s]
        // thread -> (c4 = t&31 covers c in 4s, s4 = t>>5 covers s in 4s); 4x4 micro-tile
        {
            const int c4 = t & 31;
            const int s4 = t >> 5;
            float a00=0,a01=0,a02=0,a03=0, a10=0,a11=0,a12=0,a13=0;
            float a20=0,a21=0,a22=0,a23=0, a30=0,a31=0,a32=0,a33=0;
            #pragma unroll
            for (int n = 0; n < NNB; n++) {
                const float4 g = *(const float4*)&s_G[n * L + c4 * 4];
                const float4 w = *(const float4*)&s_wp[n * S + s4 * 4];
                a00 = fmaf(g.x, w.x, a00); a01 = fmaf(g.x, w.y, a01);
                a02 = fmaf(g.x, w.z, a02); a03 = fmaf(g.x, w.w, a03);
                a10 = fmaf(g.y, w.x, a10); a11 = fmaf(g.y, w.y, a11);
                a12 = fmaf(g.y, w.z, a12); a13 = fmaf(g.y, w.w, a13);
                a20 = fmaf(g.z, w.x, a20); a21 = fmaf(g.z, w.y, a21);
                a22 = fmaf(g.z, w.z, a22); a23 = fmaf(g.z, w.w, a23);
                a30 = fmaf(g.w, w.x, a30); a31 = fmaf(g.w, w.y, a31);
                a32 = fmaf(g.w, w.z, a32); a33 = fmaf(g.w, w.w, a33);
            }
            const float b0 = s_db[s4*4+0], b1v = s_db[s4*4+1];
            const float b2v = s_db[s4*4+2], b3 = s_db[s4*4+3];
            const int cb = c4 * 4;
            float* yr0 = &s_y[(cb+0)*17 + s4*4];
            float* yr1 = &s_y[(cb+1)*17 + s4*4];
            float* yr2 = &s_y[(cb+2)*17 + s4*4];
            float* yr3 = &s_y[(cb+3)*17 + s4*4];
            yr0[0]=a00+b0; yr0[1]=a01+b1v; yr0[2]=a02+b2v; yr0[3]=a03+b3;
            yr1[0]=a10+b0; yr1[1]=a11+b1v; yr1[2]=a12+b2v; yr1[3]=a13+b3;
            yr2[0]=a20+b0; yr2[1]=a21+b1v; yr2[2]=a22+b2v; yr2[3]=a23+b3;
            yr3[0]=a30+b0; yr3[1]=a31+b1v; yr3[2]=a32+b2v; yr3[3]=a33+b3;
        }
        __syncthreads();

        // Heads: thread t = channel c; h = c/16
        {
            const int h = t >> 4;
            float yr[16];
            #pragma unroll
            for (int s = 0; s < 16; s++) yr[s] = s_y[t * 17 + s];

            float h1[32];
            #pragma unroll
            for (int m = 0; m < 32; m++) h1[m] = s_b1[h * MH + m];

            #pragma unroll
            for (int s = 0; s < 16; s++) {
                const float ys = yr[s];
                const float4* w4 = (const float4*)&s_w1[(h * S + s) * MH];
                #pragma unroll
                for (int m4 = 0; m4 < 8; m4++) {
                    const float4 w = w4[m4];
                    h1[m4*4+0] = fmaf(ys, w.x, h1[m4*4+0]);
                    h1[m4*4+1] = fmaf(ys, w.y, h1[m4*4+1]);
                    h1[m4*4+2] = fmaf(ys, w.z, h1[m4*4+2]);
                    h1[m4*4+3] = fmaf(ys, w.w, h1[m4*4+3]);
                }
            }
            float hout = s_b2[h];
            #pragma unroll
            for (int m = 0; m < 32; m++)
                hout = fmaf(gelu_f(h1[m]), s_w2[h * MH + m], hout);

            g_xmix[p * L + t] = hout + xres;
        }
    }
}

// ============================================================================
// Kernel B: hf = gelu(x_full @ ffn_w1 + b1)   (16200 x 256, K=130)
//   20 pixels / block, 256 threads (thread t = output column f).
// ============================================================================
#define PPB_B 20
__global__ void __launch_bounds__(256) ffn1_kernel(
    const float* __restrict__ x,
    const float* __restrict__ fw1,
    const float* __restrict__ fb1)
{
    __shared__ __align__(16) float s_xT[MD * PPB_B];   // [d][pp], 10.4 KB
    const int t = threadIdx.x;
    const int p0 = blockIdx.x * PPB_B;

    for (int i = t; i < MD * PPB_B; i += 256) {
        const int pp = i / MD, d = i - pp * MD;
        const float v = (d < L) ? g_xmix[(p0 + pp) * L + d]
                                : x[(p0 + pp) * MD + d];
        s_xT[d * PPB_B + pp] = v;
    }
    __syncthreads();

    float acc[PPB_B];
    const float bb = fb1[t];
    #pragma unroll
    for (int pp = 0; pp < PPB_B; pp++) acc[pp] = bb;

    for (int d = 0; d < MD; d++) {
        const float w = __ldg(&fw1[d * FH + t]);
        const float4* xv = (const float4*)&s_xT[d * PPB_B];
        #pragma unroll
        for (int p4 = 0; p4 < PPB_B / 4; p4++) {
            const float4 xx = xv[p4];
            acc[p4*4+0] = fmaf(xx.x, w, acc[p4*4+0]);
            acc[p4*4+1] = fmaf(xx.y, w, acc[p4*4+1]);
            acc[p4*4+2] = fmaf(xx.z, w, acc[p4*4+2]);
            acc[p4*4+3] = fmaf(xx.w, w, acc[p4*4+3]);
        }
    }
    #pragma unroll
    for (int pp = 0; pp < PPB_B; pp++)
        g_hf[(p0 + pp) * FH + t] = gelu_f(acc[pp]);
}

// ============================================================================
// Kernel C: x_out = hf @ ffn_w2 + b2 + x_mix -> out[:, :128]
//   24 pixels / block, 128 threads (thread t = output channel c).
// ============================================================================
#define PPB_C 24
__global__ void __launch_bounds__(128) ffn2_kernel(
    const float* __restrict__ fw2,
    const float* __restrict__ fb2,
    float* __restrict__ out)
{
    __shared__ __align__(16) float s_hT[FH * PPB_C];   // [f][pp], 24.6 KB
    const int t = threadIdx.x;
    const int p0 = blockIdx.x * PPB_C;

    for (int i = t; i < FH * PPB_C; i += 128) {
        const int pp = i / FH, f = i - pp * FH;
        s_hT[f * PPB_C + pp] = g_hf[(p0 + pp) * FH + f];
    }
    __syncthreads();

    float acc[PPB_C];
    const float bb = fb2[t];
    #pragma unroll
    for (int pp = 0; pp < PPB_C; pp++) acc[pp] = bb;

    for (int f = 0; f < FH; f++) {
        const float w = __ldg(&fw2[f * L + t]);
        const float4* hv = (const float4*)&s_hT[f * PPB_C];
        #pragma unroll
        for (int p4 = 0; p4 < PPB_C / 4; p4++) {
            const float4 hh = hv[p4];
            acc[p4*4+0] = fmaf(hh.x, w, acc[p4*4+0]);
            acc[p4*4+1] = fmaf(hh.y, w, acc[p4*4+1]);
            acc[p4*4+2] = fmaf(hh.z, w, acc[p4*4+2]);
            acc[p4*4+3] = fmaf(hh.w, w, acc[p4*4+3]);
        }
    }
    #pragma unroll
    for (int pp = 0; pp < PPB_C; pp++)
        out[(p0 + pp) * MD + t] = acc[pp] + g_xmix[(p0 + pp) * L + t];
}

// ============================================================================
// Launch
// ============================================================================
extern "C" void kernel_launch(void* const* d_in, const int* in_sizes, int n_in,
                              void* d_out, int out_size)
{
    const float* x     = (const float*)d_in[0];
    const int*   nbr   = (const int*)  d_in[1];
    const float* basis = (const float*)d_in[2];
    const float* dw    = (const float*)d_in[3];
    const float* db    = (const float*)d_in[4];
    const float* hw1   = (const float*)d_in[5];
    const float* hb1   = (const float*)d_in[6];
    const float* hw2   = (const float*)d_in[7];
    const float* hb2   = (const float*)d_in[8];
    const float* fw1   = (const float*)d_in[9];
    const float* fb1   = (const float*)d_in[10];
    const float* fw2   = (const float*)d_in[11];
    const float* fb2   = (const float*)d_in[12];
    float* out = (float*)d_out;

    disco_heads_kernel<<<P_TOT / PPB_A, 128>>>(x, nbr, basis, dw, db,
                                               hw1, hb1, hw2, hb2, out);
    ffn1_kernel<<<P_TOT / PPB_B, 256>>>(x, fw1, fb1);
    ffn2_kernel<<<P_TOT / PPB_C, 128>>>(fw2, fb2, out);
}

// round 3
// speedup vs baseline: 1.5398x; 1.5398x over previous
#include <cuda_runtime.h>
#include <math.h>

// Problem constants
#define P_TOT   16200   // H*W = 90*180
#define MD      130     // MODEL_DIM
#define L       128     // learned channels
#define NH      8
#define HD      16
#define S       16
#define K       25
#define NNB     25
#define MH      32
#define FH      256

// Scratch (allocation-free: __device__ globals)
__device__ __align__(16) float g_xmix[P_TOT * L];   // 8.3 MB
__device__ __align__(16) float g_hf  [P_TOT * FH];  // 16.6 MB

__device__ __forceinline__ float gelu_f(float v) {
    return 0.5f * v * (1.0f + erff(v * 0.70710678118654752f));
}

// group-local barrier: 128 threads, ids 1 and 2
#define BARG(gid) asm volatile("bar.sync %0, 128;" :: "r"((gid) + 1) : "memory")

// ============================================================================
// Kernel A: disco conv (refactored) + per-head MLP + residual -> g_xmix
//   256 threads = 2 independent 128-thread groups, each owns PPG pixels.
//   Per pixel:  W2[n][s] = sum_k disco_w[s][k] * basis[k][p][n]
//               y[c][s]  = sum_n G[c][n] * W2[n][s] + disco_b[s]   (registers)
//               heads:   h1 = gelu(y @ w1[h] + b1), hout = h1g @ w2[h] + b2
// ============================================================================
#define PPG 5   // pixels per group -> 10 per block -> 1620 blocks
__global__ void __launch_bounds__(256, 3) disco_heads_kernel(
    const float* __restrict__ x,
    const int*   __restrict__ nbr,
    const float* __restrict__ basis,
    const float* __restrict__ dw,
    const float* __restrict__ db,
    const float* __restrict__ hw1,
    const float* __restrict__ hb1,
    const float* __restrict__ hw2,
    const float* __restrict__ hb2,
    float* __restrict__ out)
{
    // block-wide weights
    __shared__ __align__(16) float s_dw[S * K];          // [s][k]
    __shared__ __align__(16) float s_db[S];
    __shared__ __align__(16) float s_w1[NH * S * MH];    // [h][s][m]
    __shared__ __align__(16) float s_b1[NH * MH];
    __shared__ __align__(16) float s_w2[NH * MH];
    __shared__ __align__(16) float s_b2[NH];
    // per-group workspaces
    __shared__ __align__(16) float s_basis[2][K * NNB + 3]; // [k][n]
    __shared__ __align__(16) float s_wp[2][NNB * S];        // [n][s]
    __shared__ __align__(16) float s_G[2][NNB * L];         // [n][c]
    __shared__ int   s_nbr[2][NNB];

    const int t  = threadIdx.x;
    const int g  = t >> 7;     // group 0/1
    const int lt = t & 127;    // lane-in-group = channel c

    for (int i = t; i < S * K; i += 256) s_dw[i] = dw[i];
    if (t < S) s_db[t] = db[t];
    for (int i = t; i < NH * S * MH; i += 256) s_w1[i] = hw1[i];
    for (int i = t; i < NH * MH; i += 256) { s_b1[i] = hb1[i]; s_w2[i] = hw2[i]; }
    if (t < NH) s_b2[t] = hb2[t];
    __syncthreads();

    const int p0 = blockIdx.x * (2 * PPG) + g * PPG;
    const int h  = lt >> 4;

    for (int ip = 0; ip < PPG; ip++) {
        const int p = p0 + ip;

        BARG(g);  // protect group smem reused from previous pixel

        if (lt < NNB) s_nbr[g][lt] = nbr[p * NNB + lt];
        for (int i = lt; i < K * NNB; i += 128) {
            const int k = i / NNB, n = i - k * NNB;
            s_basis[g][i] = basis[(k * P_TOT + p) * NNB + n];
        }
        BARG(g);

        // residual + sin/cos passthrough
        const float xres = x[p * MD + lt];
        if (lt < 2) out[p * MD + L + lt] = x[p * MD + L + lt];

        // gather (independent LDGs, overlap with wp compute below)
        #pragma unroll
        for (int n = 0; n < NNB; n++) {
            const int q = s_nbr[g][n];
            s_G[g][n * L + lt] = x[q * MD + lt];
        }

        // W2[n][s] = sum_k dw[s][k] * basis[k][n]   (400 outputs)
        for (int i = lt; i < NNB * S; i += 128) {
            const int n = i >> 4, s = i & 15;
            float a = 0.f;
            #pragma unroll
            for (int k = 0; k < K; k++)
                a = fmaf(s_dw[s * K + k], s_basis[g][k * NNB + n], a);
            s_wp[g][i] = a;
        }
        BARG(g);

        // y[c][s] in registers: thread lt = channel c
        float y[16];
        #pragma unroll
        for (int s = 0; s < 16; s++) y[s] = s_db[s];
        #pragma unroll
        for (int n = 0; n < NNB; n++) {
            const float gv = s_G[g][n * L + lt];          // conflict-free
            const float4 w0 = *(const float4*)&s_wp[g][n * S + 0];
            const float4 w1v = *(const float4*)&s_wp[g][n * S + 4];
            const float4 w2v = *(const float4*)&s_wp[g][n * S + 8];
            const float4 w3v = *(const float4*)&s_wp[g][n * S + 12];
            y[0]  = fmaf(gv, w0.x,  y[0]);  y[1]  = fmaf(gv, w0.y,  y[1]);
            y[2]  = fmaf(gv, w0.z,  y[2]);  y[3]  = fmaf(gv, w0.w,  y[3]);
            y[4]  = fmaf(gv, w1v.x, y[4]);  y[5]  = fmaf(gv, w1v.y, y[5]);
            y[6]  = fmaf(gv, w1v.z, y[6]);  y[7]  = fmaf(gv, w1v.w, y[7]);
            y[8]  = fmaf(gv, w2v.x, y[8]);  y[9]  = fmaf(gv, w2v.y, y[9]);
            y[10] = fmaf(gv, w2v.z, y[10]); y[11] = fmaf(gv, w2v.w, y[11]);
            y[12] = fmaf(gv, w3v.x, y[12]); y[13] = fmaf(gv, w3v.y, y[13]);
            y[14] = fmaf(gv, w3v.z, y[14]); y[15] = fmaf(gv, w3v.w, y[15]);
        }

        // heads: h = lt>>4, two m-halves of 16 to limit register pressure
        const float* w1h = &s_w1[h * S * MH];
        float hout = s_b2[h];
        #pragma unroll
        for (int half = 0; half < 2; half++) {
            const int mo = half * 16;
            float h1[16];
            #pragma unroll
            for (int j = 0; j < 16; j++) h1[j] = s_b1[h * MH + mo + j];
            #pragma unroll
            for (int s = 0; s < 16; s++) {
                const float ys = y[s];
                const float4* w4 = (const float4*)&w1h[s * MH + mo];
                #pragma unroll
                for (int j4 = 0; j4 < 4; j4++) {
                    const float4 w = w4[j4];
                    h1[j4*4+0] = fmaf(ys, w.x, h1[j4*4+0]);
                    h1[j4*4+1] = fmaf(ys, w.y, h1[j4*4+1]);
                    h1[j4*4+2] = fmaf(ys, w.z, h1[j4*4+2]);
                    h1[j4*4+3] = fmaf(ys, w.w, h1[j4*4+3]);
                }
            }
            #pragma unroll
            for (int j = 0; j < 16; j++)
                hout = fmaf(gelu_f(h1[j]), s_w2[h * MH + mo + j], hout);
        }

        g_xmix[p * L + lt] = hout + xres;
    }
}

// ============================================================================
// Kernel B: hf = gelu(x_full @ ffn_w1 + b1)   (16200 x 256, K=130)
// ============================================================================
#define PPB_B 20
__global__ void __launch_bounds__(256) ffn1_kernel(
    const float* __restrict__ x,
    const float* __restrict__ fw1,
    const float* __restrict__ fb1)
{
    __shared__ __align__(16) float s_xT[MD * PPB_B];   // [d][pp]
    const int t = threadIdx.x;
    const int p0 = blockIdx.x * PPB_B;

    for (int i = t; i < MD * PPB_B; i += 256) {
        const int pp = i / MD, d = i - pp * MD;
        const float v = (d < L) ? g_xmix[(p0 + pp) * L + d]
                                : x[(p0 + pp) * MD + d];
        s_xT[d * PPB_B + pp] = v;
    }
    __syncthreads();

    float acc[PPB_B];
    const float bb = fb1[t];
    #pragma unroll
    for (int pp = 0; pp < PPB_B; pp++) acc[pp] = bb;

    for (int d = 0; d < MD; d++) {
        const float w = __ldg(&fw1[d * FH + t]);
        const float4* xv = (const float4*)&s_xT[d * PPB_B];
        #pragma unroll
        for (int p4 = 0; p4 < PPB_B / 4; p4++) {
            const float4 xx = xv[p4];
            acc[p4*4+0] = fmaf(xx.x, w, acc[p4*4+0]);
            acc[p4*4+1] = fmaf(xx.y, w, acc[p4*4+1]);
            acc[p4*4+2] = fmaf(xx.z, w, acc[p4*4+2]);
            acc[p4*4+3] = fmaf(xx.w, w, acc[p4*4+3]);
        }
    }
    #pragma unroll
    for (int pp = 0; pp < PPB_B; pp++)
        g_hf[(p0 + pp) * FH + t] = gelu_f(acc[pp]);
}

// ============================================================================
// Kernel C: x_out = hf @ ffn_w2 + b2 + x_mix -> out[:, :128]
// ============================================================================
#define PPB_C 24
__global__ void __launch_bounds__(128) ffn2_kernel(
    const float* __restrict__ fw2,
    const float* __restrict__ fb2,
    float* __restrict__ out)
{
    __shared__ __align__(16) float s_hT[FH * PPB_C];   // [f][pp]
    const int t = threadIdx.x;
    const int p0 = blockIdx.x * PPB_C;

    for (int i = t; i < FH * PPB_C; i += 128) {
        const int pp = i / FH, f = i - pp * FH;
        s_hT[f * PPB_C + pp] = g_hf[(p0 + pp) * FH + f];
    }
    __syncthreads();

    float acc[PPB_C];
    const float bb = fb2[t];
    #pragma unroll
    for (int pp = 0; pp < PPB_C; pp++) acc[pp] = bb;

    for (int f = 0; f < FH; f++) {
        const float w = __ldg(&fw2[f * L + t]);
        const float4* hv = (const float4*)&s_hT[f * PPB_C];
        #pragma unroll
        for (int p4 = 0; p4 < PPB_C / 4; p4++) {
            const float4 hh = hv[p4];
            acc[p4*4+0] = fmaf(hh.x, w, acc[p4*4+0]);
            acc[p4*4+1] = fmaf(hh.y, w, acc[p4*4+1]);
            acc[p4*4+2] = fmaf(hh.z, w, acc[p4*4+2]);
            acc[p4*4+3] = fmaf(hh.w, w, acc[p4*4+3]);
        }
    }
    #pragma unroll
    for (int pp = 0; pp < PPB_C; pp++)
        out[(p0 + pp) * MD + t] = acc[pp] + g_xmix[(p0 + pp) * L + t];
}

// ============================================================================
// Launch
// ============================================================================
extern "C" void kernel_launch(void* const* d_in, const int* in_sizes, int n_in,
                              void* d_out, int out_size)
{
    const float* x     = (const float*)d_in[0];
    const int*   nbr   = (const int*)  d_in[1];
    const float* basis = (const float*)d_in[2];
    const float* dw    = (const float*)d_in[3];
    const float* db    = (const float*)d_in[4];
    const float* hw1   = (const float*)d_in[5];
    const float* hb1   = (const float*)d_in[6];
    const float* hw2   = (const float*)d_in[7];
    const float* hb2   = (const float*)d_in[8];
    const float* fw1   = (const float*)d_in[9];
    const float* fb1   = (const float*)d_in[10];
    const float* fw2   = (const float*)d_in[11];
    const float* fb2   = (const float*)d_in[12];
    float* out = (float*)d_out;

    disco_heads_kernel<<<P_TOT / (2 * PPG), 256>>>(x, nbr, basis, dw, db,
                                                   hw1, hb1, hw2, hb2, out);
    ffn1_kernel<<<P_TOT / PPB_B, 256>>>(x, fw1, fb1);
    ffn2_kernel<<<P_TOT / PPB_C, 128>>>(fw2, fb2, out);
}

// round 4
// speedup vs baseline: 1.7497x; 1.1363x over previous
#include <cuda_runtime.h>
#include <math.h>

// Problem constants
#define P_TOT   16200   // H*W = 90*180
#define MD      130     // MODEL_DIM
#define L       128     // learned channels
#define NH      8
#define S       16
#define K       25
#define NNB     25
#define MH      32
#define FH      256

// Scratch (allocation-free: __device__ globals)
__device__ __align__(16) float g_xL  [P_TOT * L];        // 8.3 MB packed x[:, :128]
__device__ __align__(16) float g_wp  [P_TOT * NNB * S];  // 25.9 MB precomputed W2
__device__ __align__(16) float g_xmix[P_TOT * L];        // 8.3 MB
__device__ __align__(16) float g_hf  [P_TOT * FH];       // 16.6 MB

__device__ __forceinline__ float gelu_f(float v) {
    return 0.5f * v * (1.0f + erff(v * 0.70710678118654752f));
}

#define BARG(gid) asm volatile("bar.sync %0, 128;" :: "r"((gid) + 1) : "memory")

// ============================================================================
// Kernel X: pack x[:, :128] -> g_xL (512B-aligned rows) + sin/cos passthrough
// ============================================================================
__global__ void __launch_bounds__(256) pack_kernel(
    const float* __restrict__ x, float* __restrict__ out)
{
    const int tid = blockIdx.x * 256 + threadIdx.x;
    // 16200 * 32 float4 slots = 518400
    if (tid < P_TOT * 32) {
        const int p = tid >> 5, c4 = tid & 31;
        const float* src = &x[p * MD + c4 * 4];
        float4 v = make_float4(src[0], src[1], src[2], src[3]);
        *(float4*)&g_xL[p * L + c4 * 4] = v;
    }
    if (tid < P_TOT * 2) {
        const int p = tid >> 1, c = tid & 1;
        out[p * MD + L + c] = x[p * MD + L + c];
    }
}

// ============================================================================
// Kernel W: wp[p][n][s] = sum_k dw[s][k] * basis[k][p][n]
//   256 threads = 8 pixels x 32 lanes (n = lane, active n < 25)
// ============================================================================
__global__ void __launch_bounds__(256) wp_kernel(
    const float* __restrict__ basis,
    const float* __restrict__ dw)
{
    __shared__ __align__(16) float s_dw[S * K];
    const int t = threadIdx.x;
    for (int i = t; i < S * K; i += 256) s_dw[i] = dw[i];
    __syncthreads();

    const int pp = t >> 5, n = t & 31;
    const int p = blockIdx.x * 8 + pp;
    if (n >= NNB) return;

    float b[K];
    #pragma unroll
    for (int k = 0; k < K; k++)
        b[k] = basis[(k * P_TOT + p) * NNB + n];

    float acc[S];
    #pragma unroll
    for (int s = 0; s < S; s++) {
        float a = 0.f;
        #pragma unroll
        for (int k = 0; k < K; k++)
            a = fmaf(s_dw[s * K + k], b[k], a);
        acc[s] = a;
    }
    float4* dst = (float4*)&g_wp[(p * NNB + n) * S];
    dst[0] = make_float4(acc[0],  acc[1],  acc[2],  acc[3]);
    dst[1] = make_float4(acc[4],  acc[5],  acc[6],  acc[7]);
    dst[2] = make_float4(acc[8],  acc[9],  acc[10], acc[11]);
    dst[3] = make_float4(acc[12], acc[13], acc[14], acc[15]);
}

// ============================================================================
// Kernel A: gather + y GEMV + per-head MLP + residual -> g_xmix
//   256 threads = 2 independent 128-thread groups; group = channel lane lt.
// ============================================================================
#define PPG 5
__global__ void __launch_bounds__(256, 4) disco_heads_kernel(
    const int*   __restrict__ nbr,
    const float* __restrict__ db,
    const float* __restrict__ hw1,
    const float* __restrict__ hb1,
    const float* __restrict__ hw2,
    const float* __restrict__ hb2)
{
    __shared__ __align__(16) float s_db[S];
    __shared__ __align__(16) float s_w1[NH * S * MH];    // [h][s][m] 16KB
    __shared__ __align__(16) float s_b1[NH * MH];
    __shared__ __align__(16) float s_w2[NH * MH];
    __shared__ __align__(16) float s_b2[NH];
    __shared__ __align__(16) float s_wp[2][NNB * S];     // [n][s]
    __shared__ __align__(16) float s_G[2][NNB * L];      // [n][c]
    __shared__ int s_nbrs[2][PPG * NNB];

    const int t  = threadIdx.x;
    const int g  = t >> 7;
    const int lt = t & 127;

    if (t < S) s_db[t] = db[t];
    for (int i = t; i < NH * S * MH; i += 256) s_w1[i] = hw1[i];
    for (int i = t; i < NH * MH; i += 256) { s_b1[i] = hb1[i]; s_w2[i] = hw2[i]; }
    if (t < NH) s_b2[t] = hb2[t];

    const int p0 = blockIdx.x * (2 * PPG) + g * PPG;
    for (int i = lt; i < PPG * NNB; i += 128)
        s_nbrs[g][i] = nbr[p0 * NNB + i];
    __syncthreads();

    const int h = lt >> 4;
    const int n4 = lt >> 5, c4 = lt & 31;
    const float4* xL4 = (const float4*)g_xL;
    const float4* wp4 = (const float4*)g_wp;

    for (int ip = 0; ip < PPG; ip++) {
        const int p = p0 + ip;

        BARG(g);  // guard smem reuse

        // gather: 4 neighbors in flight per pass, float4 rows
        #pragma unroll
        for (int nb = n4; nb < NNB; nb += 4) {
            const int q = s_nbrs[g][ip * NNB + nb];
            *(float4*)&s_G[g][nb * L + c4 * 4] = xL4[q * 32 + c4];
        }
        // wp tile: 400 floats = 100 float4
        if (lt < 100)
            *(float4*)&s_wp[g][lt * 4] = wp4[p * 100 + lt];
        BARG(g);

        // y[lt][s] in registers
        float y[16];
        #pragma unroll
        for (int s = 0; s < 16; s++) y[s] = s_db[s];
        #pragma unroll
        for (int n = 0; n < NNB; n++) {
            const float gv = s_G[g][n * L + lt];
            const float4 w0 = *(const float4*)&s_wp[g][n * S + 0];
            const float4 w1v = *(const float4*)&s_wp[g][n * S + 4];
            const float4 w2v = *(const float4*)&s_wp[g][n * S + 8];
            const float4 w3v = *(const float4*)&s_wp[g][n * S + 12];
            y[0]  = fmaf(gv, w0.x,  y[0]);  y[1]  = fmaf(gv, w0.y,  y[1]);
            y[2]  = fmaf(gv, w0.z,  y[2]);  y[3]  = fmaf(gv, w0.w,  y[3]);
            y[4]  = fmaf(gv, w1v.x, y[4]);  y[5]  = fmaf(gv, w1v.y, y[5]);
            y[6]  = fmaf(gv, w1v.z, y[6]);  y[7]  = fmaf(gv, w1v.w, y[7]);
            y[8]  = fmaf(gv, w2v.x, y[8]);  y[9]  = fmaf(gv, w2v.y, y[9]);
            y[10] = fmaf(gv, w2v.z, y[10]); y[11] = fmaf(gv, w2v.w, y[11]);
            y[12] = fmaf(gv, w3v.x, y[12]); y[13] = fmaf(gv, w3v.y, y[13]);
            y[14] = fmaf(gv, w3v.z, y[14]); y[15] = fmaf(gv, w3v.w, y[15]);
        }

        // heads (two m-halves of 16)
        const float* w1h = &s_w1[h * S * MH];
        float hout = s_b2[h];
        #pragma unroll
        for (int half = 0; half < 2; half++) {
            const int mo = half * 16;
            float h1[16];
            #pragma unroll
            for (int j = 0; j < 16; j++) h1[j] = s_b1[h * MH + mo + j];
            #pragma unroll
            for (int s = 0; s < 16; s++) {
                const float ys = y[s];
                const float4* w4 = (const float4*)&w1h[s * MH + mo];
                #pragma unroll
                for (int j4 = 0; j4 < 4; j4++) {
                    const float4 w = w4[j4];
                    h1[j4*4+0] = fmaf(ys, w.x, h1[j4*4+0]);
                    h1[j4*4+1] = fmaf(ys, w.y, h1[j4*4+1]);
                    h1[j4*4+2] = fmaf(ys, w.z, h1[j4*4+2]);
                    h1[j4*4+3] = fmaf(ys, w.w, h1[j4*4+3]);
                }
            }
            #pragma unroll
            for (int j = 0; j < 16; j++)
                hout = fmaf(gelu_f(h1[j]), s_w2[h * MH + mo + j], hout);
        }

        g_xmix[p * L + lt] = hout + g_xL[p * L + lt];
    }
}

// ============================================================================
// Kernel B: hf = gelu(x_full @ ffn_w1 + b1)
// ============================================================================
#define PPB_B 20
__global__ void __launch_bounds__(256) ffn1_kernel(
    const float* __restrict__ x,
    const float* __restrict__ fw1,
    const float* __restrict__ fb1)
{
    __shared__ __align__(16) float s_xT[MD * PPB_B];
    const int t = threadIdx.x;
    const int p0 = blockIdx.x * PPB_B;

    for (int i = t; i < MD * PPB_B; i += 256) {
        const int pp = i / MD, d = i - pp * MD;
        const float v = (d < L) ? g_xmix[(p0 + pp) * L + d]
                                : x[(p0 + pp) * MD + d];
        s_xT[d * PPB_B + pp] = v;
    }
    __syncthreads();

    float acc[PPB_B];
    const float bb = fb1[t];
    #pragma unroll
    for (int pp = 0; pp < PPB_B; pp++) acc[pp] = bb;

    for (int d = 0; d < MD; d++) {
        const float w = __ldg(&fw1[d * FH + t]);
        const float4* xv = (const float4*)&s_xT[d * PPB_B];
        #pragma unroll
        for (int p4 = 0; p4 < PPB_B / 4; p4++) {
            const float4 xx = xv[p4];
            acc[p4*4+0] = fmaf(xx.x, w, acc[p4*4+0]);
            acc[p4*4+1] = fmaf(xx.y, w, acc[p4*4+1]);
            acc[p4*4+2] = fmaf(xx.z, w, acc[p4*4+2]);
            acc[p4*4+3] = fmaf(xx.w, w, acc[p4*4+3]);
        }
    }
    #pragma unroll
    for (int pp = 0; pp < PPB_B; pp++)
        g_hf[(p0 + pp) * FH + t] = gelu_f(acc[pp]);
}

// ============================================================================
// Kernel C: x_out = hf @ ffn_w2 + b2 + x_mix -> out[:, :128]
// ============================================================================
#define PPB_C 24
__global__ void __launch_bounds__(128) ffn2_kernel(
    const float* __restrict__ fw2,
    const float* __restrict__ fb2,
    float* __restrict__ out)
{
    __shared__ __align__(16) float s_hT[FH * PPB_C];
    const int t = threadIdx.x;
    const int p0 = blockIdx.x * PPB_C;

    for (int i = t; i < FH * PPB_C; i += 128) {
        const int pp = i / FH, f = i - pp * FH;
        s_hT[f * PPB_C + pp] = g_hf[(p0 + pp) * FH + f];
    }
    __syncthreads();

    float acc[PPB_C];
    const float bb = fb2[t];
    #pragma unroll
    for (int pp = 0; pp < PPB_C; pp++) acc[pp] = bb;

    for (int f = 0; f < FH; f++) {
        const float w = __ldg(&fw2[f * L + t]);
        const float4* hv = (const float4*)&s_hT[f * PPB_C];
        #pragma unroll
        for (int p4 = 0; p4 < PPB_C / 4; p4++) {
            const float4 hh = hv[p4];
            acc[p4*4+0] = fmaf(hh.x, w, acc[p4*4+0]);
            acc[p4*4+1] = fmaf(hh.y, w, acc[p4*4+1]);
            acc[p4*4+2] = fmaf(hh.z, w, acc[p4*4+2]);
            acc[p4*4+3] = fmaf(hh.w, w, acc[p4*4+3]);
        }
    }
    #pragma unroll
    for (int pp = 0; pp < PPB_C; pp++)
        out[(p0 + pp) * MD + t] = acc[pp] + g_xmix[(p0 + pp) * L + t];
}

// ============================================================================
// Launch
// ============================================================================
extern "C" void kernel_launch(void* const* d_in, const int* in_sizes, int n_in,
                              void* d_out, int out_size)
{
    const float* x     = (const float*)d_in[0];
    const int*   nbr   = (const int*)  d_in[1];
    const float* basis = (const float*)d_in[2];
    const float* dw    = (const float*)d_in[3];
    const float* db    = (const float*)d_in[4];
    const float* hw1   = (const float*)d_in[5];
    const float* hb1   = (const float*)d_in[6];
    const float* hw2   = (const float*)d_in[7];
    const float* hb2   = (const float*)d_in[8];
    const float* fw1   = (const float*)d_in[9];
    const float* fb1   = (const float*)d_in[10];
    const float* fw2   = (const float*)d_in[11];
    const float* fb2   = (const float*)d_in[12];
    float* out = (float*)d_out;

    pack_kernel<<<(P_TOT * 32 + 255) / 256, 256>>>(x, out);
    wp_kernel<<<P_TOT / 8, 256>>>(basis, dw);
    disco_heads_kernel<<<P_TOT / (2 * PPG), 256>>>(nbr, db, hw1, hb1, hw2, hb2);
    ffn1_kernel<<<P_TOT / PPB_B, 256>>>(x, fw1, fb1);
    ffn2_kernel<<<P_TOT / PPB_C, 128>>>(fw2, fb2, out);
}